// round 4
// baseline (speedup 1.0000x reference)
#include <cuda_runtime.h>

// Problem constants (fixed shapes per reference)
#define B_    4
#define M_    1024
#define N_    1024
#define DX_   32
#define H_    32
#define DV_   64
#define NPAIR 16      // H_/2 pair-sums per row

#define XLA_TANH_CLAMP 7.99881172180175781f

typedef unsigned long long ull;

// Scratch (no cudaMalloc allowed)
__device__ __align__(16) float g_k2 [B_ * N_ * NPAIR];  // pair sums of k
__device__ __align__(16) float g_q2n[B_ * M_ * NPAIR];  // NEGATED pair sums of q
__device__ __align__(16) float g_Sp [B_ * 8 * DV_];     // partial sums of r over n

// ---------------------------------------------------------------------------
// XLA EmitFastTanh (f32, with_fma=true) — bit-faithful replica.
// ---------------------------------------------------------------------------
__device__ __forceinline__ float xla_fast_tanh(float x) {
    float xc = fminf(fmaxf(x, -XLA_TANH_CLAMP), XLA_TANH_CLAMP);
    float x2 = xc * xc;
    float p = fmaf(x2, -2.76076847742355e-16f, 2.00018790482477e-13f);
    p = fmaf(x2, p, -8.60467152213735e-11f);
    p = fmaf(x2, p, 5.12229709037114e-08f);
    p = fmaf(x2, p, 1.48572235717979e-05f);
    p = fmaf(x2, p, 6.37261928875436e-04f);
    p = fmaf(x2, p, 4.89352455891786e-03f);
    p = xc * p;
    float q = fmaf(x2, 1.19825839466702e-06f, 1.18534705686654e-04f);
    q = fmaf(x2, q, 2.26843463243900e-03f);
    q = fmaf(x2, q, 4.89352518554385e-03f);
    float t = p / q;                  // IEEE div.rn
    if (fabsf(x) < 0.0004f) t = x;
    return t;
}

// Packed f32x2 helpers
__device__ __forceinline__ ull add2(ull a, ull b) {
    ull d;
    asm("add.rn.f32x2 %0, %1, %2;" : "=l"(d) : "l"(a), "l"(b));
    return d;
}
__device__ __forceinline__ float hsum2(ull a) {
    float lo, hi;
    asm("mov.b64 {%0, %1}, %2;" : "=f"(lo), "=f"(hi) : "l"(a));
    return lo + hi;
}
#define ABS2_MASK 0x7FFFFFFF7FFFFFFFULL

// ---------------------------------------------------------------------------
// prep: 64 blocks x 256 threads.
//  blocks  0..15 : k pair-sum projection (256 rows each)  -> g_k2
//  blocks 16..31 : q pair-sum projection (negated)        -> g_q2n
//  blocks 32..63 : r column-sum partials (8 per batch)    -> g_Sp
// ---------------------------------------------------------------------------
__global__ __launch_bounds__(256) void prep_kernel(
    const float* __restrict__ x1,
    const float* __restrict__ x2,
    const float* __restrict__ r_in,
    const float* __restrict__ W,
    const float* __restrict__ bias
) {
    int blk = blockIdx.x, tid = threadIdx.x;

    if (blk >= 32) {
        // ---- S partials ----
        __shared__ float ps[4][DV_];
        int idx = blk - 32, batch = idx >> 3, part = idx & 7;
        int v = tid & 63, sub = tid >> 6;   // 4 subs x 32 n each
        const float* rp = r_in + ((size_t)batch * N_ + part * 128 + sub * 32) * DV_ + v;
        float s = 0.f;
        #pragma unroll
        for (int n = 0; n < 32; n++) s += rp[n * DV_];
        ps[sub][v] = s;
        __syncthreads();
        if (tid < DV_)
            g_Sp[((size_t)batch * 8 + part) * DV_ + tid] =
                (ps[0][tid] + ps[1][tid]) + (ps[2][tid] + ps[3][tid]);
        return;
    }

    // ---- pair-sum projection ----
    __shared__ float Wp[NPAIR][DX_ + 1];   // Wp[j][d] = W[2j][d]+W[2j+1][d] (padded)
    __shared__ float bp[NPAIR];
    __shared__ float xs[256 * DX_];        // 256 rows of x (unpadded for LDS.128)

    int which = (blk >= 16);
    const float* __restrict__ x  = which ? x2 : x1;
    float* __restrict__       op = which ? g_q2n : g_k2;
    float sgn  = which ? -1.f : 1.f;
    int   row0 = (blk & 15) * 256;

    for (int i = tid; i < NPAIR * DX_; i += 256) {
        int j = i >> 5, d = i & 31;
        Wp[j][d] = W[2 * j * DX_ + d] + W[(2 * j + 1) * DX_ + d];
    }
    if (tid < NPAIR) bp[tid] = bias[2 * tid] + bias[2 * tid + 1];

    {   // stage 256 x rows (float4, coalesced)
        const float4* xg = (const float4*)(x + (size_t)row0 * DX_);
        float4* xs4 = (float4*)xs;
        #pragma unroll
        for (int i = tid; i < 256 * (DX_ / 4); i += 256) xs4[i] = xg[i];
    }
    __syncthreads();

    int j  = tid & 15;           // pair index
    int rg = tid >> 4;           // 16 row groups x 16 rows
    float wreg[DX_];
    #pragma unroll
    for (int d = 0; d < DX_; d++) wreg[d] = Wp[j][d];
    float bj = bp[j];

    const float4* xs4 = (const float4*)xs;
    #pragma unroll 4
    for (int rr = 0; rr < 16; rr++) {
        int row = rg * 16 + rr;
        float s = bj;
        #pragma unroll
        for (int d4 = 0; d4 < DX_ / 4; d4++) {
            float4 xv = xs4[row * (DX_ / 4) + d4];
            s += xv.x * wreg[4 * d4 + 0];
            s += xv.y * wreg[4 * d4 + 1];
            s += xv.z * wreg[4 * d4 + 2];
            s += xv.w * wreg[4 * d4 + 3];
        }
        op[(size_t)(row0 + row) * NPAIR + j] = sgn * s;
    }
}

// ---------------------------------------------------------------------------
// Cold path: pair-sum lower bound dipped below clamp. Recompute EXACT s from
// x1/x2/W/b, apply exact correction (delta==0 when true s >= clamp).
// ---------------------------------------------------------------------------
__device__ __noinline__ void fix_pair(
    float* corr_row, const float* __restrict__ r_in,
    const float* __restrict__ x1, const float* __restrict__ x2,
    const float* __restrict__ W, const float* __restrict__ bias,
    int batch, int m, int n, float w_sat
) {
    const float* xk = x1 + ((size_t)batch * N_ + n) * DX_;
    const float* xq = x2 + ((size_t)batch * M_ + m) * DX_;
    float s = 0.f;
    for (int h = 0; h < H_; h++) {
        float kh = bias[h], qh = bias[h];
        for (int d = 0; d < DX_; d++) {
            float w = W[h * DX_ + d];
            kh = fmaf(xk[d], w, kh);
            qh = fmaf(xq[d], w, qh);
        }
        s += fabsf(kh - qh);
    }
    float wv = 1.0f + xla_fast_tanh(-s);
    float delta = wv - w_sat;
    if (delta != 0.f) {
        const float* rp = r_in + ((size_t)batch * N_ + n) * DV_;
        for (int v = 0; v < DV_; v++) atomicAdd(&corr_row[v], delta * rp[v]);
    }
}

// ---------------------------------------------------------------------------
// attn: grid 256 = B x (M/16), 256 threads = 8 warps x 2 m-rows.
// Hot path computes the pair-sum lower bound of s; bound >= clamp ==> w = w_sat
// (exact). Output = w_sat * S + corrections.
// ---------------------------------------------------------------------------
#define TM 16
#define NB 128

__global__ __launch_bounds__(256, 3) void attn_kernel(
    const float* __restrict__ r_in,
    const float* __restrict__ x1,
    const float* __restrict__ x2,
    const float* __restrict__ W,
    const float* __restrict__ bias,
    float* __restrict__ out
) {
    __shared__ float4 k4s[4][NB];       // [h4][n] pair-sum chunk, transposed
    __shared__ float  corr[TM][DV_];

    int tid   = threadIdx.x;
    int warp  = tid >> 5;
    int lane  = tid & 31;
    int batch = blockIdx.x >> 6;        // 64 m-tiles per batch
    int mtile = blockIdx.x & 63;
    int m0    = mtile * TM + warp * 2;

    const float w_sat = 1.0f + xla_fast_tanh(-XLA_TANH_CLAMP);

    for (int i = tid; i < TM * DV_; i += 256) ((float*)corr)[i] = 0.f;

    // negated q pair-sums for both rows (packed, 8 ULL each)
    ull nq0[8], nq1[8];
    {
        const ull* q0 = (const ull*)(g_q2n + ((size_t)batch * M_ + m0) * NPAIR);
        const ull* q1 = (const ull*)(g_q2n + ((size_t)batch * M_ + m0 + 1) * NPAIR);
        #pragma unroll
        for (int i = 0; i < 8; i++) { nq0[i] = q0[i]; nq1[i] = q1[i]; }
    }

    const float4* kg = (const float4*)(g_k2 + (size_t)batch * N_ * NPAIR);  // [N][4]

    int nA = tid >> 2,        hA = tid & 3;
    int nB = (tid + 256) >> 2, hB = tid & 3;   // idxB = tid+256 -> same h4 bits
    float4 pfA = kg[(size_t)nA * 4 + hA];
    float4 pfB = kg[(size_t)nB * 4 + hB];

    for (int c = 0; c < N_ / NB; c++) {
        __syncthreads();
        k4s[hA][nA] = pfA;
        k4s[hB][nB] = pfB;
        __syncthreads();
        if (c + 1 < N_ / NB) {
            size_t base = (size_t)(c + 1) * NB * 4;
            pfA = kg[base + (size_t)nA * 4 + hA];
            pfB = kg[base + (size_t)nB * 4 + hB];
        }

        #pragma unroll
        for (int ns = 0; ns < NB / 32; ns++) {
            int nl = ns * 32 + lane;
            ull kv[8];
            #pragma unroll
            for (int h4 = 0; h4 < 4; h4++) {
                float4 v = k4s[h4][nl];
                kv[2 * h4 + 0] = *(const ull*)&v.x;
                kv[2 * h4 + 1] = *(const ull*)&v.z;
            }
            ull a0 = 0, a1 = 0, b0 = 0, b1 = 0;
            #pragma unroll
            for (int jj = 0; jj < 8; jj++) {
                ull d0 = add2(kv[jj], nq0[jj]) & ABS2_MASK;
                ull d1 = add2(kv[jj], nq1[jj]) & ABS2_MASK;
                if (jj & 1) { a1 = add2(a1, d0); b1 = add2(b1, d1); }
                else        { a0 = add2(a0, d0); b0 = add2(b0, d1); }
            }
            float s0 = hsum2(add2(a0, a1));   // lower bound on true s(m0,   n)
            float s1 = hsum2(add2(b0, b1));   // lower bound on true s(m0+1, n)
            if (s0 < XLA_TANH_CLAMP)
                fix_pair(corr[warp * 2 + 0], r_in, x1, x2, W, bias,
                         batch, m0, c * NB + nl, w_sat);
            if (s1 < XLA_TANH_CLAMP)
                fix_pair(corr[warp * 2 + 1], r_in, x1, x2, W, bias,
                         batch, m0 + 1, c * NB + nl, w_sat);
        }
    }
    __syncthreads();

    // out[m][v] = w_sat * S[v] + corr[m][v],  S = sum of 8 partials
    const float* Sp = g_Sp + (size_t)batch * 8 * DV_;
    float* op = out + ((size_t)batch * M_ + mtile * TM) * DV_;
    for (int i = tid; i < TM * DV_; i += 256) {
        int ml = i >> 6, v = i & 63;
        float S = 0.f;
        #pragma unroll
        for (int p = 0; p < 8; p++) S += Sp[p * DV_ + v];
        op[(size_t)ml * DV_ + v] = fmaf(w_sat, S, corr[ml][v]);
    }
}

// ---------------------------------------------------------------------------
// Launch: bind inputs by element count (robust to metadata ordering).
// ---------------------------------------------------------------------------
extern "C" void kernel_launch(void* const* d_in, const int* in_sizes, int n_in,
                              void* d_out, int out_size) {
    const float* x1 = nullptr;
    const float* x2 = nullptr;
    const float* r  = nullptr;
    const float* W  = nullptr;
    const float* b  = nullptr;

    for (int i = 0; i < n_in; i++) {
        int sz = in_sizes[i];
        const float* p = (const float*)d_in[i];
        if (sz == B_ * N_ * DV_)      { r = p; }
        else if (sz == H_ * DX_)      { W = p; }
        else if (sz == H_)            { b = p; }
        else if (sz == B_ * N_ * DX_) { if (!x1) x1 = p; else x2 = p; }
    }
    if (!x1 || !x2 || !r || !W || !b) {
        x1 = (const float*)d_in[0];
        x2 = (const float*)d_in[1];
        r  = (const float*)d_in[2];
        W  = (const float*)d_in[3];
        b  = (const float*)d_in[4];
    }

    float* out = (float*)d_out;
    (void)out_size;

    prep_kernel<<<64, 256>>>(x1, x2, r, W, b);           // k2, q2n, Sp
    attn_kernel<<<B_ * (M_ / TM), 256>>>(r, x1, x2, W, b, out);
}

// round 5
// speedup vs baseline: 2.9170x; 2.9170x over previous
#include <cuda_runtime.h>

// Problem constants (fixed shapes per reference)
#define B_    4
#define M_    1024
#define N_    1024
#define DX_   32
#define H_    32
#define DV_   64
#define NPAIR 16      // H_/2 pair-sums per row

#define XLA_TANH_CLAMP 7.99881172180175781f

typedef unsigned long long ull;

// Scratch (no cudaMalloc allowed)
__device__ __align__(16) float g_k2 [B_ * N_ * NPAIR];  // pair sums of k
__device__ __align__(16) float g_q2n[B_ * M_ * NPAIR];  // NEGATED pair sums of q
__device__ __align__(16) float g_Sp [B_ * 8 * DV_];     // partial sums of r over n

// ---------------------------------------------------------------------------
// XLA EmitFastTanh (f32, with_fma=true) — bit-faithful replica.
// ---------------------------------------------------------------------------
__device__ __forceinline__ float xla_fast_tanh(float x) {
    float xc = fminf(fmaxf(x, -XLA_TANH_CLAMP), XLA_TANH_CLAMP);
    float x2 = xc * xc;
    float p = fmaf(x2, -2.76076847742355e-16f, 2.00018790482477e-13f);
    p = fmaf(x2, p, -8.60467152213735e-11f);
    p = fmaf(x2, p, 5.12229709037114e-08f);
    p = fmaf(x2, p, 1.48572235717979e-05f);
    p = fmaf(x2, p, 6.37261928875436e-04f);
    p = fmaf(x2, p, 4.89352455891786e-03f);
    p = xc * p;
    float q = fmaf(x2, 1.19825839466702e-06f, 1.18534705686654e-04f);
    q = fmaf(x2, q, 2.26843463243900e-03f);
    q = fmaf(x2, q, 4.89352518554385e-03f);
    float t = p / q;                  // IEEE div.rn
    if (fabsf(x) < 0.0004f) t = x;
    return t;
}

// Packed f32x2 helpers (operands stay in registers; no address-taking)
__device__ __forceinline__ ull add2(ull a, ull b) {
    ull d;
    asm("add.rn.f32x2 %0, %1, %2;" : "=l"(d) : "l"(a), "l"(b));
    return d;
}
__device__ __forceinline__ float hsum2(ull a) {
    float lo, hi;
    asm("mov.b64 {%0, %1}, %2;" : "=f"(lo), "=f"(hi) : "l"(a));
    return lo + hi;
}
#define ABS2_MASK 0x7FFFFFFF7FFFFFFFULL

// ---------------------------------------------------------------------------
// prep: 96 blocks x 256 threads.
//  blocks  0..63 : pair-sum projections. 2 threads per row (8 pairs each).
//                  rows 0..4095 = k (from x1), 4096..8191 = q negated (x2).
//  blocks 64..95 : r column-sum partials (8 per batch) -> g_Sp
// ---------------------------------------------------------------------------
__global__ __launch_bounds__(256) void prep_kernel(
    const float* __restrict__ x1,
    const float* __restrict__ x2,
    const float* __restrict__ r_in,
    const float* __restrict__ W,
    const float* __restrict__ bias
) {
    int blk = blockIdx.x, tid = threadIdx.x;

    if (blk >= 64) {
        // ---- S partials ----
        __shared__ float ps[4][DV_];
        int idx = blk - 64, batch = idx >> 3, part = idx & 7;
        int v = tid & 63, sub = tid >> 6;   // 4 subs x 32 n each
        const float* rp = r_in + ((size_t)batch * N_ + part * 128 + sub * 32) * DV_ + v;
        float s = 0.f;
        #pragma unroll
        for (int n = 0; n < 32; n++) s += rp[n * DV_];
        ps[sub][v] = s;
        __syncthreads();
        if (tid < DV_)
            g_Sp[((size_t)batch * 8 + part) * DV_ + tid] =
                (ps[0][tid] + ps[1][tid]) + (ps[2][tid] + ps[3][tid]);
        return;
    }

    // ---- pair-sum projection: 128 rows per block, 2 threads/row ----
    __shared__ float Wp[NPAIR][DX_ + 1];   // Wp[j][d] = W[2j][d]+W[(2j+1)][d]
    __shared__ float bp[NPAIR];

    for (int i = tid; i < NPAIR * DX_; i += 256) {
        int j = i >> 5, d = i & 31;
        Wp[j][d] = W[2 * j * DX_ + d] + W[(2 * j + 1) * DX_ + d];
    }
    if (tid < NPAIR) bp[tid] = bias[2 * tid] + bias[2 * tid + 1];
    __syncthreads();

    int row  = blk * 128 + (tid >> 1);     // 0..8191
    int half = tid & 1;                    // pairs half*8 .. half*8+7
    int isq  = row >= 4096;
    int lrow = row - (isq ? 4096 : 0);
    const float* x = (isq ? x2 : x1) + (size_t)lrow * DX_;
    float* op = (isq ? g_q2n : g_k2) + (size_t)lrow * NPAIR + half * 8;
    float sgn = isq ? -1.f : 1.f;

    // x row into registers (float4 loads; values consumed by name, no &)
    float xr[DX_];
    {
        const float4* xg = (const float4*)x;
        #pragma unroll
        for (int i = 0; i < DX_ / 4; i++) {
            float4 v = xg[i];
            xr[4*i+0] = v.x; xr[4*i+1] = v.y; xr[4*i+2] = v.z; xr[4*i+3] = v.w;
        }
    }

    float s[8];
    #pragma unroll
    for (int jj = 0; jj < 8; jj++) {
        int j = half * 8 + jj;
        float acc = bp[j];
        #pragma unroll
        for (int d = 0; d < DX_; d++) acc = fmaf(xr[d], Wp[j][d], acc);
        s[jj] = sgn * acc;
    }
    float4* o4 = (float4*)op;
    o4[0] = make_float4(s[0], s[1], s[2], s[3]);
    o4[1] = make_float4(s[4], s[5], s[6], s[7]);
}

// ---------------------------------------------------------------------------
// Cold path (deferred, out of hot loop): recompute EXACT s from x1/x2/W/b,
// apply exact correction (delta==0 when true s >= clamp).
// ---------------------------------------------------------------------------
__device__ __noinline__ void fix_pair(
    float* corr_row, const float* __restrict__ r_in,
    const float* __restrict__ x1, const float* __restrict__ x2,
    const float* __restrict__ W, const float* __restrict__ bias,
    int batch, int m, int n, float w_sat
) {
    const float* xk = x1 + ((size_t)batch * N_ + n) * DX_;
    const float* xq = x2 + ((size_t)batch * M_ + m) * DX_;
    float s = 0.f;
    for (int h = 0; h < H_; h++) {
        float kh = bias[h], qh = bias[h];
        for (int d = 0; d < DX_; d++) {
            float w = W[h * DX_ + d];
            kh = fmaf(xk[d], w, kh);
            qh = fmaf(xq[d], w, qh);
        }
        s += fabsf(kh - qh);
    }
    float wv = 1.0f + xla_fast_tanh(-s);
    float delta = wv - w_sat;
    if (delta != 0.f) {
        const float* rp = r_in + ((size_t)batch * N_ + n) * DV_;
        for (int v = 0; v < DV_; v++) atomicAdd(&corr_row[v], delta * rp[v]);
    }
}

// ---------------------------------------------------------------------------
// attn: grid 256 = B x (M/16), 256 threads = 8 warps x 2 m-rows.
// Hot path: pair-sum lower bound of s via packed f32x2; bound >= clamp ==>
// w == w_sat exactly (XLA clamp). Flags below-clamp groups in a bitmask,
// handles them AFTER the mainloop. Output = w_sat * S + corrections.
// ---------------------------------------------------------------------------
#define TM 16
#define NB 128

__global__ __launch_bounds__(256, 3) void attn_kernel(
    const float* __restrict__ r_in,
    const float* __restrict__ x1,
    const float* __restrict__ x2,
    const float* __restrict__ W,
    const float* __restrict__ bias,
    float* __restrict__ out
) {
    __shared__ ulonglong2 ks[4][NB];    // [vec][n] transposed k2 chunk
    __shared__ float corr[TM][DV_];

    int tid   = threadIdx.x;
    int warp  = tid >> 5;
    int lane  = tid & 31;
    int batch = blockIdx.x >> 6;        // 64 m-tiles per batch
    int mtile = blockIdx.x & 63;
    int m0    = mtile * TM + warp * 2;

    const float w_sat = 1.0f + xla_fast_tanh(-XLA_TANH_CLAMP);

    for (int i = tid; i < TM * DV_; i += 256) ((float*)corr)[i] = 0.f;

    // negated q pair-sums for both rows (8 ull each, straight u64 loads)
    ull nq0[8], nq1[8];
    {
        const ull* q0 = (const ull*)(g_q2n + ((size_t)batch * M_ + m0) * NPAIR);
        const ull* q1 = (const ull*)(g_q2n + ((size_t)batch * M_ + m0 + 1) * NPAIR);
        #pragma unroll
        for (int i = 0; i < 8; i++) { nq0[i] = q0[i]; nq1[i] = q1[i]; }
    }

    // k2 rows as ulonglong2: [N][4] vectors
    const ulonglong2* kg = (const ulonglong2*)(g_k2 + (size_t)batch * N_ * NPAIR);

    int nA = tid >> 2,         vA = tid & 3;     // 512 vec slots per chunk
    int nB = (tid + 256) >> 2, vB = tid & 3;
    ulonglong2 pfA = kg[(size_t)nA * 4 + vA];
    ulonglong2 pfB = kg[(size_t)nB * 4 + vB];

    unsigned mask0 = 0, mask1 = 0;   // per-group "bound below clamp" flags

    for (int c = 0; c < N_ / NB; c++) {
        __syncthreads();
        ks[vA][nA] = pfA;            // STS.128 from register pair
        ks[vB][nB] = pfB;
        __syncthreads();
        if (c + 1 < N_ / NB) {
            size_t base = (size_t)(c + 1) * NB * 4;
            pfA = kg[base + (size_t)nA * 4 + vA];
            pfB = kg[base + (size_t)nB * 4 + vB];
        }

        #pragma unroll
        for (int ns = 0; ns < NB / 32; ns++) {
            int nl = ns * 32 + lane;
            ull a0 = 0, a1 = 0, b0 = 0, b1 = 0;
            #pragma unroll
            for (int v = 0; v < 4; v++) {
                ulonglong2 kv = ks[v][nl];       // LDS.128 -> two u64 regs
                ull d;
                d = add2(kv.x, nq0[2*v+0]) & ABS2_MASK; a0 = add2(a0, d);
                d = add2(kv.y, nq0[2*v+1]) & ABS2_MASK; a1 = add2(a1, d);
                d = add2(kv.x, nq1[2*v+0]) & ABS2_MASK; b0 = add2(b0, d);
                d = add2(kv.y, nq1[2*v+1]) & ABS2_MASK; b1 = add2(b1, d);
            }
            float s0 = hsum2(add2(a0, a1));      // lower bound s(m0,   n)
            float s1 = hsum2(add2(b0, b1));      // lower bound s(m0+1, n)
            int g = c * 4 + ns;                  // 0..31
            if (s0 < XLA_TANH_CLAMP) mask0 |= 1u << g;
            if (s1 < XLA_TANH_CLAMP) mask1 |= 1u << g;
        }
    }

    // Deferred rare path: exact recompute only for flagged (group, lane) pairs.
    while (mask0) {
        int g = __ffs(mask0) - 1; mask0 &= mask0 - 1;
        int n = (g >> 2) * NB + (g & 3) * 32 + lane;
        fix_pair(corr[warp * 2 + 0], r_in, x1, x2, W, bias, batch, m0, n, w_sat);
    }
    while (mask1) {
        int g = __ffs(mask1) - 1; mask1 &= mask1 - 1;
        int n = (g >> 2) * NB + (g & 3) * 32 + lane;
        fix_pair(corr[warp * 2 + 1], r_in, x1, x2, W, bias, batch, m0 + 1, n, w_sat);
    }
    __syncthreads();

    // out[m][v] = w_sat * S[v] + corr[m][v],  S = sum of 8 partials
    const float* Sp = g_Sp + (size_t)batch * 8 * DV_;
    float* op = out + ((size_t)batch * M_ + mtile * TM) * DV_;
    for (int i = tid; i < TM * DV_; i += 256) {
        int ml = i >> 6, v = i & 63;
        float S = 0.f;
        #pragma unroll
        for (int p = 0; p < 8; p++) S += Sp[p * DV_ + v];
        op[(size_t)ml * DV_ + v] = fmaf(w_sat, S, corr[ml][v]);
    }
}

// ---------------------------------------------------------------------------
// Launch: bind inputs by element count (robust to metadata ordering).
// ---------------------------------------------------------------------------
extern "C" void kernel_launch(void* const* d_in, const int* in_sizes, int n_in,
                              void* d_out, int out_size) {
    const float* x1 = nullptr;
    const float* x2 = nullptr;
    const float* r  = nullptr;
    const float* W  = nullptr;
    const float* b  = nullptr;

    for (int i = 0; i < n_in; i++) {
        int sz = in_sizes[i];
        const float* p = (const float*)d_in[i];
        if (sz == B_ * N_ * DV_)      { r = p; }
        else if (sz == H_ * DX_)      { W = p; }
        else if (sz == H_)            { b = p; }
        else if (sz == B_ * N_ * DX_) { if (!x1) x1 = p; else x2 = p; }
    }
    if (!x1 || !x2 || !r || !W || !b) {
        x1 = (const float*)d_in[0];
        x2 = (const float*)d_in[1];
        r  = (const float*)d_in[2];
        W  = (const float*)d_in[3];
        b  = (const float*)d_in[4];
    }

    float* out = (float*)d_out;
    (void)out_size;

    prep_kernel<<<96, 256>>>(x1, x2, r, W, b);           // k2, q2n, Sp
    attn_kernel<<<B_ * (M_ / TM), 256>>>(r, x1, x2, W, b, out);
}

// round 6
// speedup vs baseline: 6.0960x; 2.0898x over previous
#include <cuda_runtime.h>

// Problem constants (fixed shapes per reference)
#define B_    4
#define M_    1024
#define N_    1024
#define DX_   32
#define H_    32
#define DV_   64
#define NPAIR 16      // H_/2 pair-sums per row

#define XLA_TANH_CLAMP 7.99881172180175781f

typedef unsigned long long ull;

// Scratch (no cudaMalloc allowed)
__device__ __align__(16) float g_k2 [B_ * N_ * NPAIR];  // pair sums of k
__device__ __align__(16) float g_q2n[B_ * M_ * NPAIR];  // NEGATED pair sums of q
__device__ __align__(16) float g_kf [B_ * N_ * H_];     // full k projection
__device__ __align__(16) float g_qfn[B_ * M_ * H_];     // NEGATED full q projection
__device__ __align__(16) float g_Sp [B_ * 8 * DV_];     // partial sums of r over n

// ---------------------------------------------------------------------------
// XLA EmitFastTanh (f32, with_fma=true) — bit-faithful replica.
// ---------------------------------------------------------------------------
__device__ __forceinline__ float xla_fast_tanh(float x) {
    float xc = fminf(fmaxf(x, -XLA_TANH_CLAMP), XLA_TANH_CLAMP);
    float x2 = xc * xc;
    float p = fmaf(x2, -2.76076847742355e-16f, 2.00018790482477e-13f);
    p = fmaf(x2, p, -8.60467152213735e-11f);
    p = fmaf(x2, p, 5.12229709037114e-08f);
    p = fmaf(x2, p, 1.48572235717979e-05f);
    p = fmaf(x2, p, 6.37261928875436e-04f);
    p = fmaf(x2, p, 4.89352455891786e-03f);
    p = xc * p;
    float q = fmaf(x2, 1.19825839466702e-06f, 1.18534705686654e-04f);
    q = fmaf(x2, q, 2.26843463243900e-03f);
    q = fmaf(x2, q, 4.89352518554385e-03f);
    float t = p / q;                  // IEEE div.rn
    if (fabsf(x) < 0.0004f) t = x;
    return t;
}

// Packed f32x2 helpers (operands stay in registers; no address-taking)
__device__ __forceinline__ ull add2(ull a, ull b) {
    ull d;
    asm("add.rn.f32x2 %0, %1, %2;" : "=l"(d) : "l"(a), "l"(b));
    return d;
}
__device__ __forceinline__ float hsum2(ull a) {
    float lo, hi;
    asm("mov.b64 {%0, %1}, %2;" : "=f"(lo), "=f"(hi) : "l"(a));
    return lo + hi;
}
#define ABS2_MASK 0x7FFFFFFF7FFFFFFFULL

// ---------------------------------------------------------------------------
// prep: 160 blocks x 256 threads.
//  blocks   0..127 : projections. 64 rows/block, 4 threads/row, 8 h each.
//                    rows 0..4095 = k (x1), 4096..8191 = q NEGATED (x2).
//                    Writes full proj (g_kf/g_qfn) AND pair sums (g_k2/g_q2n).
//  blocks 128..159 : r column-sum partials (8 per batch) -> g_Sp
// ---------------------------------------------------------------------------
__global__ __launch_bounds__(256) void prep_kernel(
    const float* __restrict__ x1,
    const float* __restrict__ x2,
    const float* __restrict__ r_in,
    const float* __restrict__ W,
    const float* __restrict__ bias
) {
    int blk = blockIdx.x, tid = threadIdx.x;

    if (blk >= 128) {
        // ---- S partials ----
        __shared__ float ps[4][DV_];
        int idx = blk - 128, batch = idx >> 3, part = idx & 7;
        int v = tid & 63, sub = tid >> 6;   // 4 subs x 32 n each
        const float* rp = r_in + ((size_t)batch * N_ + part * 128 + sub * 32) * DV_ + v;
        float s = 0.f;
        #pragma unroll
        for (int n = 0; n < 32; n++) s += rp[n * DV_];
        ps[sub][v] = s;
        __syncthreads();
        if (tid < DV_)
            g_Sp[((size_t)batch * 8 + part) * DV_ + tid] =
                (ps[0][tid] + ps[1][tid]) + (ps[2][tid] + ps[3][tid]);
        return;
    }

    // ---- projection ----
    __shared__ float Ws[H_][DX_ + 1];   // Ws[h][d] = W[h][d] (padded)
    __shared__ float bs[H_];

    for (int i = tid; i < H_ * DX_; i += 256) {
        int h = i >> 5, d = i & 31;
        Ws[h][d] = W[i];
    }
    if (tid < H_) bs[tid] = bias[tid];
    __syncthreads();

    int row  = blk * 64 + (tid >> 2);    // 0..8191
    int quad = tid & 3;                  // h = quad*8 .. quad*8+7
    int isq  = row >= 4096;
    int lrow = row - (isq ? 4096 : 0);
    const float* x = (isq ? x2 : x1) + (size_t)lrow * DX_;
    float sgn = isq ? -1.f : 1.f;

    // x row into registers
    float xr[DX_];
    {
        const float4* xg = (const float4*)x;
        #pragma unroll
        for (int i = 0; i < DX_ / 4; i++) {
            float4 v = xg[i];
            xr[4*i+0] = v.x; xr[4*i+1] = v.y; xr[4*i+2] = v.z; xr[4*i+3] = v.w;
        }
    }

    float acc[8];
    #pragma unroll
    for (int jj = 0; jj < 8; jj++) {
        int h = quad * 8 + jj;
        float a = bs[h];
        #pragma unroll
        for (int d = 0; d < DX_; d++) a = fmaf(xr[d], Ws[h][d], a);
        acc[jj] = sgn * a;
    }

    // full projection (signed): 2 x float4
    {
        float4* of = (float4*)((isq ? g_qfn : g_kf) + (size_t)lrow * H_ + quad * 8);
        of[0] = make_float4(acc[0], acc[1], acc[2], acc[3]);
        of[1] = make_float4(acc[4], acc[5], acc[6], acc[7]);
    }
    // pair sums (signed): 1 x float4
    {
        float4* op = (float4*)((isq ? g_q2n : g_k2) + (size_t)lrow * NPAIR + quad * 4);
        op[0] = make_float4(acc[0] + acc[1], acc[2] + acc[3],
                            acc[4] + acc[5], acc[6] + acc[7]);
    }
}

// ---------------------------------------------------------------------------
// Cold path (deferred): exact s from stored projections (cheap!), correction
// only if truly below clamp (delta == 0 otherwise by XLA clamp semantics).
// ---------------------------------------------------------------------------
__device__ __noinline__ void fix_pair(
    float* corr_row, const float* __restrict__ r_in,
    int batch, int m, int n, float w_sat
) {
    const float4* kp = (const float4*)(g_kf  + ((size_t)batch * N_ + n) * H_);
    const float4* qp = (const float4*)(g_qfn + ((size_t)batch * M_ + m) * H_);
    float s = 0.f;
    #pragma unroll
    for (int i = 0; i < H_ / 4; i++) {
        float4 a = kp[i], b = qp[i];   // b is already -q
        s += fabsf(a.x + b.x) + fabsf(a.y + b.y)
           + fabsf(a.z + b.z) + fabsf(a.w + b.w);
    }
    if (s < XLA_TANH_CLAMP) {
        float wv = 1.0f + xla_fast_tanh(-s);
        float delta = wv - w_sat;
        if (delta != 0.f) {
            const float* rp = r_in + ((size_t)batch * N_ + n) * DV_;
            for (int v = 0; v < DV_; v++) atomicAdd(&corr_row[v], delta * rp[v]);
        }
    }
}

// ---------------------------------------------------------------------------
// attn: grid 256 = B x (M/16), 256 threads = 8 warps x 2 m-rows.
// Hot path: pair-sum lower bound of s via packed f32x2; bound >= clamp ==>
// w == w_sat exactly. Below-clamp groups flagged in bitmask, fixed AFTER the
// mainloop. Output = w_sat * S + corrections.
// ---------------------------------------------------------------------------
#define TM 16
#define NB 128

__global__ __launch_bounds__(256, 3) void attn_kernel(
    const float* __restrict__ r_in,
    float* __restrict__ out
) {
    __shared__ ulonglong2 ks[4][NB];    // [vec][n] transposed k2 chunk
    __shared__ float corr[TM][DV_];

    int tid   = threadIdx.x;
    int warp  = tid >> 5;
    int lane  = tid & 31;
    int batch = blockIdx.x >> 6;        // 64 m-tiles per batch
    int mtile = blockIdx.x & 63;
    int m0    = mtile * TM + warp * 2;

    const float w_sat = 1.0f + xla_fast_tanh(-XLA_TANH_CLAMP);

    for (int i = tid; i < TM * DV_; i += 256) ((float*)corr)[i] = 0.f;

    // negated q pair-sums for both rows (8 ull each)
    ull nq0[8], nq1[8];
    {
        const ull* q0 = (const ull*)(g_q2n + ((size_t)batch * M_ + m0) * NPAIR);
        const ull* q1 = (const ull*)(g_q2n + ((size_t)batch * M_ + m0 + 1) * NPAIR);
        #pragma unroll
        for (int i = 0; i < 8; i++) { nq0[i] = q0[i]; nq1[i] = q1[i]; }
    }

    const ulonglong2* kg = (const ulonglong2*)(g_k2 + (size_t)batch * N_ * NPAIR);

    int nA = tid >> 2,         vA = tid & 3;
    int nB = (tid + 256) >> 2, vB = tid & 3;
    ulonglong2 pfA = kg[(size_t)nA * 4 + vA];
    ulonglong2 pfB = kg[(size_t)nB * 4 + vB];

    unsigned mask0 = 0, mask1 = 0;   // per-group "bound below clamp" flags

    for (int c = 0; c < N_ / NB; c++) {
        __syncthreads();
        ks[vA][nA] = pfA;
        ks[vB][nB] = pfB;
        __syncthreads();
        if (c + 1 < N_ / NB) {
            size_t base = (size_t)(c + 1) * NB * 4;
            pfA = kg[base + (size_t)nA * 4 + vA];
            pfB = kg[base + (size_t)nB * 4 + vB];
        }

        #pragma unroll
        for (int ns = 0; ns < NB / 32; ns++) {
            int nl = ns * 32 + lane;
            ull a0 = 0, a1 = 0, b0 = 0, b1 = 0;
            #pragma unroll
            for (int v = 0; v < 4; v++) {
                ulonglong2 kv = ks[v][nl];
                ull d;
                d = add2(kv.x, nq0[2*v+0]) & ABS2_MASK; a0 = add2(a0, d);
                d = add2(kv.y, nq0[2*v+1]) & ABS2_MASK; a1 = add2(a1, d);
                d = add2(kv.x, nq1[2*v+0]) & ABS2_MASK; b0 = add2(b0, d);
                d = add2(kv.y, nq1[2*v+1]) & ABS2_MASK; b1 = add2(b1, d);
            }
            float s0 = hsum2(add2(a0, a1));
            float s1 = hsum2(add2(b0, b1));
            int g = c * 4 + ns;
            if (s0 < XLA_TANH_CLAMP) mask0 |= 1u << g;
            if (s1 < XLA_TANH_CLAMP) mask1 |= 1u << g;
        }
    }

    // Deferred rare path (cheap now: reads stored projections)
    while (mask0) {
        int g = __ffs(mask0) - 1; mask0 &= mask0 - 1;
        int n = (g >> 2) * NB + (g & 3) * 32 + lane;
        fix_pair(corr[warp * 2 + 0], r_in, batch, m0, n, w_sat);
    }
    while (mask1) {
        int g = __ffs(mask1) - 1; mask1 &= mask1 - 1;
        int n = (g >> 2) * NB + (g & 3) * 32 + lane;
        fix_pair(corr[warp * 2 + 1], r_in, batch, m0 + 1, n, w_sat);
    }
    __syncthreads();

    // out[m][v] = w_sat * S[v] + corr[m][v]
    const float* Sp = g_Sp + (size_t)batch * 8 * DV_;
    float* op = out + ((size_t)batch * M_ + mtile * TM) * DV_;
    for (int i = tid; i < TM * DV_; i += 256) {
        int ml = i >> 6, v = i & 63;
        float S = 0.f;
        #pragma unroll
        for (int p = 0; p < 8; p++) S += Sp[p * DV_ + v];
        op[(size_t)ml * DV_ + v] = fmaf(w_sat, S, corr[ml][v]);
    }
}

// ---------------------------------------------------------------------------
// Launch: bind inputs by element count (robust to metadata ordering).
// ---------------------------------------------------------------------------
extern "C" void kernel_launch(void* const* d_in, const int* in_sizes, int n_in,
                              void* d_out, int out_size) {
    const float* x1 = nullptr;
    const float* x2 = nullptr;
    const float* r  = nullptr;
    const float* W  = nullptr;
    const float* b  = nullptr;

    for (int i = 0; i < n_in; i++) {
        int sz = in_sizes[i];
        const float* p = (const float*)d_in[i];
        if (sz == B_ * N_ * DV_)      { r = p; }
        else if (sz == H_ * DX_)      { W = p; }
        else if (sz == H_)            { b = p; }
        else if (sz == B_ * N_ * DX_) { if (!x1) x1 = p; else x2 = p; }
    }
    if (!x1 || !x2 || !r || !W || !b) {
        x1 = (const float*)d_in[0];
        x2 = (const float*)d_in[1];
        r  = (const float*)d_in[2];
        W  = (const float*)d_in[3];
        b  = (const float*)d_in[4];
    }

    float* out = (float*)d_out;
    (void)out_size;

    prep_kernel<<<160, 256>>>(x1, x2, r, W, b);      // kf, qfn, k2, q2n, Sp
    attn_kernel<<<B_ * (M_ / TM), 256>>>(r, out);
}